// round 5
// baseline (speedup 1.0000x reference)
#include <cuda_runtime.h>
#include <cstdint>

// GrCNetSpmm: out[r, f] += edge_w[e, f] for r = edge[0][e].
// Strategy: counting-sort edges by row, then warp-per-row gather+sum.
// This removes the 205MB RED.v4 scatter stream (which was lane-issue bound
// at ~50us) and replaces it with a DRAM-bound coalesced gather (~35us).

#define MAX_N 65536
#define MAX_E (1 << 20)

__device__ int g_is64;              // 1 if edge indices are int64
__device__ int g_cnt[MAX_N];        // per-row edge count
__device__ int g_ofs[MAX_N + 1];    // exclusive prefix (row segment starts)
__device__ int g_cur[MAX_N];        // scatter cursors
__device__ int g_perm[MAX_E];       // edge ids sorted by row

// ---- pass 1: zero counters + dtype detect -------------------------------
__global__ void init_kernel(const int* __restrict__ edge_w32, int N) {
    if (blockIdx.x == 0 && threadIdx.x < 32) {
        int v = edge_w32[2 * threadIdx.x + 1];
        unsigned m = __ballot_sync(0xFFFFFFFFu, v != 0);
        if (threadIdx.x == 0) g_is64 = (m == 0) ? 1 : 0;
    }
    int i = blockIdx.x * blockDim.x + threadIdx.x;
    if (i < N) g_cnt[i] = 0;
}

__device__ __forceinline__ int load_row(const void* rows, int e, int is64) {
    return is64 ? (int)__ldg((const long long*)rows + e)
                : __ldg((const int*)rows + e);
}

// ---- pass 2: histogram ---------------------------------------------------
__global__ void hist_kernel(const void* __restrict__ rows, int E, int N) {
    int i = blockIdx.x * blockDim.x + threadIdx.x;
    if (i >= E) return;
    int r = load_row(rows, i, g_is64);
    if ((unsigned)r < (unsigned)N) atomicAdd(&g_cnt[r], 1);
}

// ---- pass 3: exclusive scan (single block, 1024 threads) ------------------
__global__ void __launch_bounds__(1024) scan_kernel(int N) {
    __shared__ int part[1024];
    int t = threadIdx.x;
    int C = (N + 1023) / 1024;
    int lo = t * C;
    int hi = lo + C < N ? lo + C : N;
    int s = 0;
    for (int i = lo; i < hi; i++) s += g_cnt[i];
    part[t] = s;
    __syncthreads();
    // Hillis-Steele inclusive scan over the 1024 partials
    for (int d = 1; d < 1024; d <<= 1) {
        int v = (t >= d) ? part[t - d] : 0;
        __syncthreads();
        part[t] += v;
        __syncthreads();
    }
    int run = (t == 0) ? 0 : part[t - 1];
    for (int i = lo; i < hi; i++) {
        int c = g_cnt[i];
        g_ofs[i] = run;
        g_cur[i] = run;
        run += c;
    }
    if (t == 1023) g_ofs[N] = part[1023];
}

// ---- pass 4: scatter edge ids into row-sorted order -----------------------
__global__ void scatter_kernel(const void* __restrict__ rows, int E, int N) {
    int i = blockIdx.x * blockDim.x + threadIdx.x;
    if (i >= E) return;
    int r = load_row(rows, i, g_is64);
    if ((unsigned)r < (unsigned)N) {
        int p = atomicAdd(&g_cur[r], 1);
        g_perm[p] = i;
    }
}

// ---- pass 5: warp-per-row gather + sum ------------------------------------
// F == 64 floats: each lane owns one float2 chunk -> 256B coalesced per edge.
__global__ void __launch_bounds__(256) gather_kernel(
        const float2* __restrict__ w, float2* __restrict__ out, int N) {
    int warp = (blockIdx.x * blockDim.x + threadIdx.x) >> 5;
    int lane = threadIdx.x & 31;
    if (warp >= N) return;
    int s = g_ofs[warp];
    int e = g_ofs[warp + 1];
    float2 acc = make_float2(0.f, 0.f);
    int k = s;
    for (; k + 4 <= e; k += 4) {                 // 4-deep MLP
        int e0 = __ldg(g_perm + k + 0);
        int e1 = __ldg(g_perm + k + 1);
        int e2 = __ldg(g_perm + k + 2);
        int e3 = __ldg(g_perm + k + 3);
        float2 v0 = __ldg(w + (size_t)e0 * 32 + lane);
        float2 v1 = __ldg(w + (size_t)e1 * 32 + lane);
        float2 v2 = __ldg(w + (size_t)e2 * 32 + lane);
        float2 v3 = __ldg(w + (size_t)e3 * 32 + lane);
        acc.x += (v0.x + v1.x) + (v2.x + v3.x);
        acc.y += (v0.y + v1.y) + (v2.y + v3.y);
    }
    for (; k < e; k++) {
        int e0 = __ldg(g_perm + k);
        float2 v = __ldg(w + (size_t)e0 * 32 + lane);
        acc.x += v.x;
        acc.y += v.y;
    }
    out[(size_t)warp * 32 + lane] = acc;
}

// ---- fallback (generic shapes): zero + RED scatter -------------------------
__global__ void zero_out_kernel(float4* __restrict__ out, int n4) {
    int i = blockIdx.x * blockDim.x + threadIdx.x;
    if (i < n4) out[i] = make_float4(0.f, 0.f, 0.f, 0.f);
}
__global__ void segsum_red_kernel(const void* __restrict__ rows_raw,
                                  const float4* __restrict__ w,
                                  float* __restrict__ out,
                                  int total, int F4, int F, int N) {
    int i = blockIdx.x * blockDim.x + threadIdx.x;
    if (i >= total) return;
    int e = i / F4, j = i % F4;
    int r = load_row(rows_raw, e, g_is64);
    float4 v = __ldg(w + i);
    if ((unsigned)r < (unsigned)N) {
        float* dst = out + (size_t)r * F + (size_t)j * 4;
        asm volatile("red.global.add.v4.f32 [%0], {%1, %2, %3, %4};"
                     :: "l"(dst), "f"(v.x), "f"(v.y), "f"(v.z), "f"(v.w)
                     : "memory");
    }
}

extern "C" void kernel_launch(void* const* d_in, const int* in_sizes, int n_in,
                              void* d_out, int out_size) {
    const void* edge = d_in[0];                    // [2, E]; edge[0] = rows
    const float* edge_w = (const float*)d_in[1];   // [E, F] f32

    int E = in_sizes[0] / 2;
    int F = in_sizes[1] / E;                       // 64
    int N = out_size / F;                          // 50000

    if (F == 64 && E <= MAX_E && N <= MAX_N) {
        int threads = 256;
        init_kernel<<<(N + threads - 1) / threads, threads>>>((const int*)edge, N);
        hist_kernel<<<(E + threads - 1) / threads, threads>>>(edge, E, N);
        scan_kernel<<<1, 1024>>>(N);
        scatter_kernel<<<(E + threads - 1) / threads, threads>>>(edge, E, N);
        int warps_per_block = threads / 32;
        int blocks = (N + warps_per_block - 1) / warps_per_block;
        gather_kernel<<<blocks, threads>>>((const float2*)edge_w,
                                           (float2*)d_out, N);
    } else {
        // generic fallback: RED scatter
        int F4 = F / 4;
        int total = E * F4;
        int n4 = out_size / 4;
        int threads = 256;
        init_kernel<<<1, 32>>>((const int*)edge, 0);   // dtype detect only
        zero_out_kernel<<<(n4 + threads - 1) / threads, threads>>>(
            (float4*)d_out, n4);
        segsum_red_kernel<<<(total + threads - 1) / threads, threads>>>(
            edge, (const float4*)edge_w, (float*)d_out, total, F4, F, N);
    }
}

// round 6
// speedup vs baseline: 3.0882x; 3.0882x over previous
#include <cuda_runtime.h>
#include <cstdint>

// GrCNetSpmm: out[r, f] += edge_w[e, f] for r = edge[0][e].
// Strategy: per-row linked lists (build via atomicExch), then warp gather:
// removes the 205MB RED scatter stream (lane-issue bound ~52us) in favor of
// a DRAM-bound coalesced gather with register accumulation.

#define MAX_N 65536
#define MAX_E (1 << 20)

__device__ int g_is64;            // 1 if edge indices are int64
__device__ int g_head[MAX_N];     // per-row list head (edge id or -1)
__device__ int g_next[MAX_E];     // per-edge next pointer

__device__ __forceinline__ int load_row(const void* rows, int e, int is64) {
    return is64 ? (int)__ldg((const long long*)rows + e)
                : __ldg((const int*)rows + e);
}

// ---- pass 1: head = -1 + dtype detect ------------------------------------
// int64 data (values < 2^31): odd int32 words all zero; random int32 rows not.
__global__ void init_kernel(const int* __restrict__ edge_w32, int N) {
    if (blockIdx.x == 0 && threadIdx.x < 32) {
        int v = edge_w32[2 * threadIdx.x + 1];
        unsigned m = __ballot_sync(0xFFFFFFFFu, v != 0);
        if (threadIdx.x == 0) g_is64 = (m == 0) ? 1 : 0;
    }
    int i = blockIdx.x * blockDim.x + threadIdx.x;
    if (i < N) g_head[i] = -1;
}

// ---- pass 2: build linked lists (U=4 front-batched for MLP) ---------------
template <int U>
__global__ void __launch_bounds__(256)
build_kernel(const void* __restrict__ rows, int E, int N) {
    const int is64 = g_is64;
    const int stride = gridDim.x * blockDim.x;
    const int i0 = blockIdx.x * blockDim.x + threadIdx.x;

    int e[U], r[U], prev[U];
    bool ok[U];
    #pragma unroll
    for (int u = 0; u < U; u++) {                 // batch index loads
        e[u] = i0 + u * stride;
        ok[u] = (e[u] < E);
        r[u] = ok[u] ? load_row(rows, e[u], is64) : 0;
        ok[u] = ok[u] && ((unsigned)r[u] < (unsigned)N);
    }
    #pragma unroll
    for (int u = 0; u < U; u++)                   // batch exchanges
        if (ok[u]) prev[u] = atomicExch(&g_head[r[u]], e[u]);
    #pragma unroll
    for (int u = 0; u < U; u++)                   // batch next-stores
        if (ok[u]) g_next[e[u]] = prev[u];
}

// ---- pass 3: gather. 2 rows per warp, 16 lanes x float4 per row. ----------
// Chain hop (next[]) is L2-resident; data loads (256B coalesced per edge)
// are independent of the hop, so DRAM stream overlaps the chase.
__global__ void __launch_bounds__(256)
gather_kernel(const float4* __restrict__ w, float4* __restrict__ out, int N) {
    int gwarp = (blockIdx.x * blockDim.x + threadIdx.x) >> 5;
    int lane = threadIdx.x & 31;
    int row = gwarp * 2 + (lane >> 4);
    int sub = lane & 15;                          // float4 chunk within row
    if (row >= N) return;

    float4 acc = make_float4(0.f, 0.f, 0.f, 0.f);
    int e = g_head[row];
    while (e >= 0) {
        float4 v = __ldg(w + (size_t)e * 16 + sub);
        int en = __ldg(g_next + e);               // independent of v
        acc.x += v.x; acc.y += v.y; acc.z += v.z; acc.w += v.w;
        e = en;
    }
    out[(size_t)row * 16 + sub] = acc;
}

// ---- fallback (generic shapes): zero + RED scatter -------------------------
__global__ void zero_out_kernel(float4* __restrict__ out, int n4) {
    int i = blockIdx.x * blockDim.x + threadIdx.x;
    if (i < n4) out[i] = make_float4(0.f, 0.f, 0.f, 0.f);
}
__global__ void segsum_red_kernel(const void* __restrict__ rows_raw,
                                  const float4* __restrict__ w,
                                  float* __restrict__ out,
                                  int total, int F4, int F, int N) {
    int i = blockIdx.x * blockDim.x + threadIdx.x;
    if (i >= total) return;
    int e = i / F4, j = i % F4;
    int r = load_row(rows_raw, e, g_is64);
    float4 v = __ldg(w + i);
    if ((unsigned)r < (unsigned)N) {
        float* dst = out + (size_t)r * F + (size_t)j * 4;
        asm volatile("red.global.add.v4.f32 [%0], {%1, %2, %3, %4};"
                     :: "l"(dst), "f"(v.x), "f"(v.y), "f"(v.z), "f"(v.w)
                     : "memory");
    }
}

extern "C" void kernel_launch(void* const* d_in, const int* in_sizes, int n_in,
                              void* d_out, int out_size) {
    const void* edge = d_in[0];                    // [2, E]; edge[0] = rows
    const float* edge_w = (const float*)d_in[1];   // [E, F] f32

    int E = in_sizes[0] / 2;
    int F = in_sizes[1] / E;                       // 64
    int N = out_size / F;                          // 50000

    if (F == 64 && E <= MAX_E && N <= MAX_N) {
        int threads = 256;
        init_kernel<<<(N + threads - 1) / threads, threads>>>(
            (const int*)edge, N);

        constexpr int U = 4;
        int work = (E + U - 1) / U;
        build_kernel<U><<<(work + threads - 1) / threads, threads>>>(
            edge, E, N);

        int rows_per_block = (threads / 32) * 2;   // 2 rows per warp
        int blocks = (N + rows_per_block - 1) / rows_per_block;
        gather_kernel<<<blocks, threads>>>((const float4*)edge_w,
                                           (float4*)d_out, N);
    } else {
        int F4 = F / 4;
        int total = E * F4;
        int n4 = out_size / 4;
        int threads = 256;
        init_kernel<<<1, 32>>>((const int*)edge, 0);   // dtype detect only
        zero_out_kernel<<<(n4 + threads - 1) / threads, threads>>>(
            (float4*)d_out, n4);
        segsum_red_kernel<<<(total + threads - 1) / threads, threads>>>(
            edge, (const float4*)edge_w, (float*)d_out, total, F4, F, N);
    }
}

// round 7
// speedup vs baseline: 3.2091x; 1.0391x over previous
#include <cuda_runtime.h>
#include <cstdint>

// GrCNetSpmm: out[r, f] += edge_w[e, f] for r = edge[0][e].
// 2-launch pipeline:
//   build : per-row linked lists via atomicExch (head encodes edge_id+1, 0=empty)
//   gather: 4 rows per warp, register-accumulate, write out, RESET head to 0
// head reset inside gather restores the all-zero invariant for the next call,
// eliminating the init launch (small kernels cost ~4-5us of pure overhead).

#define MAX_N 65536
#define MAX_E (1 << 20)

__device__ int g_head[MAX_N];     // 0 = empty, else edge_id+1 (zero-init by CUDA)
__device__ int g_next[MAX_E];     // raw previous head value (same encoding)
__device__ int g_is64_fb;         // fallback path dtype flag

__device__ __forceinline__ int load_row(const void* rows, int e, int is64) {
    return is64 ? (int)__ldg((const long long*)rows + e)
                : __ldg((const int*)rows + e);
}

// ---- pass 1: build linked lists (U-way front-batched atomics) -------------
// Per-block dtype detect: odd int32 words of int64 row data are all zero
// (values < 2^31); random int32 rows are not.
template <int U>
__global__ void __launch_bounds__(256)
build_kernel(const void* __restrict__ rows, int E, int N) {
    __shared__ int s_is64;
    if (threadIdx.x < 32) {
        int v = ((const int*)rows)[2 * threadIdx.x + 1];
        unsigned m = __ballot_sync(0xFFFFFFFFu, v != 0);
        if (threadIdx.x == 0) s_is64 = (m == 0) ? 1 : 0;
    }
    __syncthreads();
    const int is64 = s_is64;

    const int stride = gridDim.x * blockDim.x;
    const int i0 = blockIdx.x * blockDim.x + threadIdx.x;

    int e[U], r[U], prev[U];
    bool ok[U];
    #pragma unroll
    for (int u = 0; u < U; u++) {                 // batch index loads
        e[u] = i0 + u * stride;
        ok[u] = (e[u] < E);
        r[u] = ok[u] ? load_row(rows, e[u], is64) : 0;
        ok[u] = ok[u] && ((unsigned)r[u] < (unsigned)N);
    }
    #pragma unroll
    for (int u = 0; u < U; u++)                   // batch exchanges (deep MLP)
        if (ok[u]) prev[u] = atomicExch(&g_head[r[u]], e[u] + 1);
    #pragma unroll
    for (int u = 0; u < U; u++)                   // batch next-stores
        if (ok[u]) g_next[e[u]] = prev[u];
}

// ---- pass 2: gather. 4 rows/warp, 8 lanes x 2 float4 per row. -------------
// next[] chain is L2-resident (234cyc) and pipelines under the 577cyc DRAM
// data fetch; 4 chains/warp for latency hiding. Resets head to 0 at the end.
__global__ void __launch_bounds__(256)
gather_kernel(const float4* __restrict__ w, float4* __restrict__ out, int N) {
    int gwarp = (blockIdx.x * blockDim.x + threadIdx.x) >> 5;
    int lane = threadIdx.x & 31;
    int row = gwarp * 4 + (lane >> 3);
    int sub = lane & 7;                           // float4 chunk 0..7
    if (row >= N) return;

    float4 a0 = make_float4(0.f, 0.f, 0.f, 0.f);
    float4 a1 = make_float4(0.f, 0.f, 0.f, 0.f);

    int h = g_head[row];
    while (h > 0) {
        int e = h - 1;
        const float4* p = w + (size_t)e * 16 + sub;
        int hn = __ldg(g_next + e);               // issue chain hop first
        float4 v0 = __ldg(p);
        float4 v1 = __ldg(p + 8);
        a0.x += v0.x; a0.y += v0.y; a0.z += v0.z; a0.w += v0.w;
        a1.x += v1.x; a1.y += v1.y; a1.z += v1.z; a1.w += v1.w;
        h = hn;
    }
    out[(size_t)row * 16 + sub]     = a0;
    out[(size_t)row * 16 + 8 + sub] = a1;
    if (sub == 0) g_head[row] = 0;                // restore empty invariant
}

// ---- fallback (generic shapes): detect + zero + RED scatter ----------------
__global__ void detect_fb_kernel(const int* __restrict__ w32) {
    int v = w32[2 * threadIdx.x + 1];
    unsigned m = __ballot_sync(0xFFFFFFFFu, v != 0);
    if (threadIdx.x == 0) g_is64_fb = (m == 0) ? 1 : 0;
}
__global__ void zero_out_kernel(float4* __restrict__ out, int n4) {
    int i = blockIdx.x * blockDim.x + threadIdx.x;
    if (i < n4) out[i] = make_float4(0.f, 0.f, 0.f, 0.f);
}
__global__ void segsum_red_kernel(const void* __restrict__ rows_raw,
                                  const float4* __restrict__ w,
                                  float* __restrict__ out,
                                  int total, int F4, int F, int N) {
    int i = blockIdx.x * blockDim.x + threadIdx.x;
    if (i >= total) return;
    int e = i / F4, j = i % F4;
    int r = load_row(rows_raw, e, g_is64_fb);
    float4 v = __ldg(w + i);
    if ((unsigned)r < (unsigned)N) {
        float* dst = out + (size_t)r * F + (size_t)j * 4;
        asm volatile("red.global.add.v4.f32 [%0], {%1, %2, %3, %4};"
                     :: "l"(dst), "f"(v.x), "f"(v.y), "f"(v.z), "f"(v.w)
                     : "memory");
    }
}

extern "C" void kernel_launch(void* const* d_in, const int* in_sizes, int n_in,
                              void* d_out, int out_size) {
    const void* edge = d_in[0];                    // [2, E]; edge[0] = rows
    const float* edge_w = (const float*)d_in[1];   // [E, F] f32

    int E = in_sizes[0] / 2;
    int F = in_sizes[1] / E;                       // 64
    int N = out_size / F;                          // 50000

    if (F == 64 && E <= MAX_E && N <= MAX_N) {
        int threads = 256;

        constexpr int U = 8;
        int work = (E + U - 1) / U;
        build_kernel<U><<<(work + threads - 1) / threads, threads>>>(
            edge, E, N);

        int rows_per_block = (threads / 32) * 4;   // 4 rows per warp
        int blocks = (N + rows_per_block - 1) / rows_per_block;
        gather_kernel<<<blocks, threads>>>((const float4*)edge_w,
                                           (float4*)d_out, N);
    } else {
        int F4 = F / 4;
        int total = E * F4;
        int n4 = out_size / 4;
        int threads = 256;
        detect_fb_kernel<<<1, 32>>>((const int*)edge);
        zero_out_kernel<<<(n4 + threads - 1) / threads, threads>>>(
            (float4*)d_out, n4);
        segsum_red_kernel<<<(total + threads - 1) / threads, threads>>>(
            edge, (const float4*)edge_w, (float*)d_out, total, F4, F, N);
    }
}